// round 4
// baseline (speedup 1.0000x reference)
#include <cuda_runtime.h>
#include <math.h>

#define NB 2
#define NN 384
#define DD 128
#define NSQ (NN*NN)
#define ROWS_E (NB*NSQ)      // 294912
#define ROWS_N (NB*NN)       // 768
#define TILES_E (ROWS_E/32)  // 9216
#define SCALE 0.08838834764831845f

// ---- scratch (device globals; no runtime allocation) ----
__device__ __align__(256) float g_qkvn[ROWS_N*384];
__device__ __align__(256) float g_qkve[(size_t)ROWS_E*512];   // 604 MB
__device__ __align__(256) float g_attn[ROWS_N*DD];
__device__ __align__(256) float g_mJ[ROWS_N*DD];
__device__ __align__(256) float g_mI[ROWS_N*DD];
__device__ __align__(256) float g_P[ROWS_N*DD];
__device__ __align__(256) float g_Q[ROWS_N*DD];
__device__ __align__(256) float g_buf[(size_t)ROWS_E*DD];     // 151 MB
__device__ __align__(256) float g_h[(size_t)ROWS_E*256];      // 302 MB

// ---- helpers ----
__device__ __forceinline__ unsigned long long pk2(float a){unsigned long long r;asm("mov.b64 %0,{%1,%1};":"=l"(r):"f"(a));return r;}
__device__ __forceinline__ void fma2(unsigned long long&d,unsigned long long a,unsigned long long b){asm("fma.rn.f32x2 %0,%1,%2,%0;":"+l"(d):"l"(a),"l"(b));}
__device__ __forceinline__ float2 up2(unsigned long long v){float2 f;asm("mov.b64 {%0,%1},%2;":"=f"(f.x),"=f"(f.y):"l"(v));return f;}
__device__ __forceinline__ float geluf(float x){return 0.5f*x*(1.f+erff(x*0.70710678118654752f));}
__device__ __forceinline__ float wsum(float v){
    #pragma unroll
    for(int o=16;o;o>>=1)v+=__shfl_xor_sync(0xffffffffu,v,o);return v;}
__device__ __forceinline__ float wmax(float v){
    #pragma unroll
    for(int o=16;o;o>>=1)v=fmaxf(v,__shfl_xor_sync(0xffffffffu,v,o));return v;}

// ---- K1: node qkv (768 x 384, K=128) ----
__global__ __launch_bounds__(384) void k_qkvn(const float* __restrict__ node,const float* __restrict__ W){
    int row=blockIdx.x,c=threadIdx.x;
    __shared__ float s[DD];
    if(c<DD)s[c]=node[row*DD+c];
    __syncthreads();
    float a=0.f;
    #pragma unroll 8
    for(int k=0;k<DD;k++)a+=s[k]*W[k*384+c];
    g_qkvn[row*384+c]=a;
}

// ---- K2: edge qkv GEMM (294912 x 512, K=128), half (256 cols) per blockIdx.y ----
__global__ __launch_bounds__(256,1) void k_qkve(const float* __restrict__ edge,const float* __restrict__ W){
    extern __shared__ float sm[];
    float* sW=sm;float* sX=sm+DD*256;
    int tid=threadIdx.x,half=blockIdx.y,rg=tid>>5,lane=tid&31;
    float4* sW4=(float4*)sW;const float4* W4=(const float4*)W;
    for(int i=tid;i<DD*64;i+=256){int k=i>>6,c=i&63;sW4[i]=W4[k*128+half*64+c];}
    const ulonglong2* sWu=(const ulonglong2*)sW;
    float4* sX4=(float4*)sX;const float4* E4=(const float4*)edge;
    for(int t=blockIdx.x;t<TILES_E;t+=gridDim.x){
        size_t r0=(size_t)t*32;
        __syncthreads();
        for(int i=tid;i<1024;i+=256)sX4[i]=E4[r0*32+i];
        __syncthreads();
        unsigned long long acc[4][4]={};
        #pragma unroll 2
        for(int k=0;k<DD;k++){
            ulonglong2 b0=sWu[k*64+lane],b1=sWu[k*64+32+lane];
            #pragma unroll
            for(int r=0;r<4;r++){
                unsigned long long a=pk2(sX[(rg*4+r)*DD+k]);
                fma2(acc[r][0],a,b0.x);fma2(acc[r][1],a,b0.y);
                fma2(acc[r][2],a,b1.x);fma2(acc[r][3],a,b1.y);
            }
        }
        #pragma unroll
        for(int r=0;r<4;r++){
            size_t row=r0+rg*4+r;
            float2 a0=up2(acc[r][0]),a1=up2(acc[r][1]),a2=up2(acc[r][2]),a3=up2(acc[r][3]);
            ((float4*)g_qkve)[row*128+half*64+lane]=make_float4(a0.x,a0.y,a1.x,a1.y);
            ((float4*)g_qkve)[row*128+half*64+32+lane]=make_float4(a2.x,a2.y,a3.x,a3.y);
        }
    }
}

// ---- K3: attention, one warp per (b,h,i) ----
__global__ __launch_bounds__(128) void k_attn(){
    int w=threadIdx.x>>5,lane=threadIdx.x&31;
    int gw=blockIdx.x*4+w;
    int b=gw/(8*NN),rr=gw%(8*NN),h=rr/NN,i=rr%NN;
    const float* qb=g_qkvn+(b*NN+i)*384+h*48;
    float qv[16];
    #pragma unroll
    for(int c=0;c<16;c++)qv[c]=qb[c];
    const float* eb=g_qkve+((size_t)(b*NN+i)*NN)*512+h*64;
    float dl[12];
    #pragma unroll
    for(int t=0;t<12;t++){
        int j=lane+32*t;
        const float4* e4=(const float4*)(eb+(size_t)j*512);
        const float4* k4=(const float4*)(g_qkvn+(b*NN+j)*384+h*48+16);
        float d=0.f;
        #pragma unroll
        for(int q=0;q<4;q++){
            float4 eq=e4[q],ek=e4[4+q],kk=k4[q];
            d+=(qv[4*q]+eq.x)*(kk.x+ek.x)+(qv[4*q+1]+eq.y)*(kk.y+ek.y)
              +(qv[4*q+2]+eq.z)*(kk.z+ek.z)+(qv[4*q+3]+eq.w)*(kk.w+ek.w);
        }
        dl[t]=d*SCALE;
    }
    float m=dl[0];
    #pragma unroll
    for(int t=1;t<12;t++)m=fmaxf(m,dl[t]);
    m=wmax(m);
    float s=0.f,out[16];
    #pragma unroll
    for(int c=0;c<16;c++)out[c]=0.f;
    #pragma unroll
    for(int t=0;t<12;t++){
        int j=lane+32*t;
        float p=expf(dl[t]-m);s+=p;
        const float4* e4=(const float4*)(eb+(size_t)j*512);
        const float4* v4=(const float4*)(g_qkvn+(b*NN+j)*384+h*48+32);
        #pragma unroll
        for(int q=0;q<4;q++){
            float4 ev=e4[8+q],em=e4[12+q],vn=v4[q];
            out[4*q]+=p*(vn.x*em.x+ev.x);out[4*q+1]+=p*(vn.y*em.y+ev.y);
            out[4*q+2]+=p*(vn.z*em.z+ev.z);out[4*q+3]+=p*(vn.w*em.w+ev.w);
        }
    }
    s=wsum(s);
    float inv=1.f/s;
    #pragma unroll
    for(int c=0;c<16;c++){
        float v=wsum(out[c]);
        if(lane==0)g_attn[(b*NN+i)*DD+h*16+c]=v*inv;
    }
}

// ---- K4: node updates (lin0 + LN + MLP + LN) ----
__global__ __launch_bounds__(128) void k_node(const float* __restrict__ node,const float* __restrict__ w0,const float* __restrict__ b0,
    const float* __restrict__ g0,const float* __restrict__ be0,const float* __restrict__ g1,const float* __restrict__ be1,
    const float* __restrict__ w1,const float* __restrict__ w2,const float* __restrict__ b2,float* __restrict__ x){
    int row=blockIdx.x,c=threadIdx.x;
    __shared__ float sa[DD],sx[DD],sh[256],sr[8];
    sa[c]=g_attn[row*DD+c];
    __syncthreads();
    float y=b0[c];
    #pragma unroll 4
    for(int k=0;k<DD;k++)y+=sa[k]*w0[k*DD+c];
    float r=node[row*DD+c]+y;
    float t=wsum(r);if((c&31)==0)sr[c>>5]=t;__syncthreads();
    float mean=(sr[0]+sr[1]+sr[2]+sr[3])*(1.f/DD);
    float d=r-mean;
    t=wsum(d*d);if((c&31)==0)sr[4+(c>>5)]=t;__syncthreads();
    float x0=d*rsqrtf((sr[4]+sr[5]+sr[6]+sr[7])*(1.f/DD)+1e-5f)*g0[c]+be0[c];
    sx[c]=x0;__syncthreads();
    float h0=0.f,h1=0.f;
    #pragma unroll 4
    for(int k=0;k<DD;k++){float v=sx[k];h0+=v*w1[k*256+c];h1+=v*w1[k*256+c+128];}
    sh[c]=geluf(h0);sh[c+128]=geluf(h1);
    __syncthreads();
    float z=b2[c];
    #pragma unroll 4
    for(int k=0;k<256;k++)z+=sh[k]*w2[k*DD+c];
    float r2=x0+z;
    __syncthreads();
    t=wsum(r2);if((c&31)==0)sr[c>>5]=t;__syncthreads();
    float m2=(sr[0]+sr[1]+sr[2]+sr[3])*(1.f/DD);
    float d2=r2-m2;
    t=wsum(d2*d2);if((c&31)==0)sr[4+(c>>5)]=t;__syncthreads();
    x[row*DD+c]=d2*rsqrtf((sr[4]+sr[5]+sr[6]+sr[7])*(1.f/DD)+1e-5f)*g1[c]+be1[c];
}

// ---- K5: edge means over j (y=0) and over i (y=1) ----
__global__ __launch_bounds__(128) void k_means(const float* __restrict__ edge){
    int bi=blockIdx.x,c=threadIdx.x,b=bi/NN,r=bi%NN;
    float s=0.f;
    if(blockIdx.y==0){
        const float* p=edge+((size_t)(b*NN+r)*NN)*DD+c;
        for(int j=0;j<NN;j++)s+=p[(size_t)j*DD];
        g_mJ[bi*DD+c]=s*(1.f/NN);
    }else{
        const float* p=edge+((size_t)b*NSQ+r)*DD+c;
        for(int i=0;i<NN;i++)s+=p[(size_t)i*NN*DD];
        g_mI[bi*DD+c]=s*(1.f/NN);
    }
}

// ---- K6: per-node broadcast rows P(i), Q(j) ----
__global__ __launch_bounds__(128) void k_PQ(const float* __restrict__ x,const float* __restrict__ ws,const float* __restrict__ bs,
    const float* __restrict__ wt,const float* __restrict__ bt,const float* __restrict__ wer,const float* __restrict__ wec){
    int bi=blockIdx.x,c=threadIdx.x;
    __shared__ float sx[DD],sj[DD],si[DD];
    sx[c]=x[bi*DD+c];sj[c]=g_mJ[bi*DD+c];si[c]=g_mI[bi*DD+c];
    __syncthreads();
    float P=bs[c],Q=bt[c];
    #pragma unroll 4
    for(int k=0;k<DD;k++){
        P+=sx[k]*ws[k*DD+c]+sj[k]*wer[k*DD+c];
        Q+=sx[k]*wt[k*DD+c]+si[k]*wec[k*DD+c];
    }
    g_P[bi*DD+c]=P;g_Q[bi*DD+c]=Q;
}

// ---- K7: e = gelu(concat(edge,edgeT)@We + be + P[i] + Q[j]) -> g_buf ----
__global__ __launch_bounds__(256,1) void k_e1(const float* __restrict__ edge,const float* __restrict__ We,const float* __restrict__ be){
    extern __shared__ float sm[];
    float* sW=sm;float* sX=sm+256*DD;
    __shared__ float sbe[DD];
    int tid=threadIdx.x,rg=tid>>5,lane=tid&31;
    float4* sW4=(float4*)sW;const float4* W4=(const float4*)We;
    for(int i=tid;i<256*32;i+=256)sW4[i]=W4[i];
    if(tid<DD)sbe[tid]=be[tid];
    const ulonglong2* sWu=(const ulonglong2*)sW;
    float4* sX4=(float4*)sX;const float4* E4=(const float4*)edge;
    for(int t=blockIdx.x;t<TILES_E;t+=gridDim.x){
        int r0=t*32,b=r0/NSQ,rem=r0%NSQ,i=rem/NN,j0=rem%NN;
        __syncthreads();
        for(int lr=rg;lr<32;lr+=8){
            int j=j0+lr;
            sX4[lr*64+lane]=E4[((size_t)(b*NN+i)*NN+j)*32+lane];
            sX4[lr*64+32+lane]=E4[((size_t)(b*NN+j)*NN+i)*32+lane];
        }
        __syncthreads();
        unsigned long long acc[4][2]={};
        #pragma unroll 2
        for(int k=0;k<256;k++){
            ulonglong2 bv=sWu[k*32+lane];
            #pragma unroll
            for(int r=0;r<4;r++){
                unsigned long long a=pk2(sX[(rg*4+r)*256+k]);
                fma2(acc[r][0],a,bv.x);fma2(acc[r][1],a,bv.y);
            }
        }
        float4 p4=((const float4*)g_P)[(b*NN+i)*32+lane];
        #pragma unroll
        for(int r=0;r<4;r++){
            int lr=rg*4+r,j=j0+lr;
            float4 q4=((const float4*)g_Q)[(b*NN+j)*32+lane];
            float2 a0=up2(acc[r][0]),a1=up2(acc[r][1]);
            float4 o;
            o.x=geluf(a0.x+sbe[4*lane]+p4.x+q4.x);
            o.y=geluf(a0.y+sbe[4*lane+1]+p4.y+q4.y);
            o.z=geluf(a1.x+sbe[4*lane+2]+p4.z+q4.z);
            o.w=geluf(a1.y+sbe[4*lane+3]+p4.w+q4.w);
            ((float4*)g_buf)[((size_t)r0+lr)*32+lane]=o;
        }
    }
}

// ---- K8: t = LN(edge + g_buf@W1 + b1) -> tout (d_out edge region) ----
__global__ __launch_bounds__(256,1) void k_e2(const float* __restrict__ edge,const float* __restrict__ W1,const float* __restrict__ b1,
    const float* __restrict__ g,const float* __restrict__ bb,float* __restrict__ tout){
    extern __shared__ float sm[];
    float* sW=sm;float* sX=sm+DD*DD;
    __shared__ float sb[DD],sg[DD],sbb[DD];
    int tid=threadIdx.x,rg=tid>>5,lane=tid&31;
    float4* sW4=(float4*)sW;const float4* W4=(const float4*)W1;
    for(int i=tid;i<DD*32;i+=256)sW4[i]=W4[i];
    if(tid<DD){sb[tid]=b1[tid];sg[tid]=g[tid];sbb[tid]=bb[tid];}
    const ulonglong2* sWu=(const ulonglong2*)sW;
    float4* sX4=(float4*)sX;
    for(int t=blockIdx.x;t<TILES_E;t+=gridDim.x){
        size_t r0=(size_t)t*32;
        __syncthreads();
        for(int i=tid;i<1024;i+=256)sX4[i]=((const float4*)g_buf)[r0*32+i];
        __syncthreads();
        unsigned long long acc[4][2]={};
        #pragma unroll 2
        for(int k=0;k<DD;k++){
            ulonglong2 bv=sWu[k*32+lane];
            #pragma unroll
            for(int r=0;r<4;r++){
                unsigned long long a=pk2(sX[(rg*4+r)*DD+k]);
                fma2(acc[r][0],a,bv.x);fma2(acc[r][1],a,bv.y);
            }
        }
        #pragma unroll
        for(int r=0;r<4;r++){
            size_t row=r0+rg*4+r;
            float4 e4=((const float4*)edge)[row*32+lane];
            float2 a0=up2(acc[r][0]),a1=up2(acc[r][1]);
            float v0=a0.x+sb[4*lane]+e4.x,v1=a0.y+sb[4*lane+1]+e4.y;
            float v2=a1.x+sb[4*lane+2]+e4.z,v3=a1.y+sb[4*lane+3]+e4.w;
            float mean=wsum(v0+v1+v2+v3)*(1.f/DD);
            v0-=mean;v1-=mean;v2-=mean;v3-=mean;
            float var=wsum(v0*v0+v1*v1+v2*v2+v3*v3)*(1.f/DD);
            float rs=rsqrtf(var+1e-5f);
            float4 o;
            o.x=v0*rs*sg[4*lane]+sbb[4*lane];
            o.y=v1*rs*sg[4*lane+1]+sbb[4*lane+1];
            o.z=v2*rs*sg[4*lane+2]+sbb[4*lane+2];
            o.w=v3*rs*sg[4*lane+3]+sbb[4*lane+3];
            ((float4*)tout)[row*32+lane]=o;
        }
    }
}

// ---- K9: h = gelu(t @ e1w1)  (294912 x 256, K=128) -> g_h ----
__global__ __launch_bounds__(256,1) void k_e3(const float* __restrict__ tin,const float* __restrict__ W){
    extern __shared__ float sm[];
    float* sW=sm;float* sX=sm+DD*256;
    int tid=threadIdx.x,rg=tid>>5,lane=tid&31;
    float4* sW4=(float4*)sW;const float4* W4=(const float4*)W;
    for(int i=tid;i<DD*64;i+=256)sW4[i]=W4[i];
    const ulonglong2* sWu=(const ulonglong2*)sW;
    float4* sX4=(float4*)sX;
    for(int t=blockIdx.x;t<TILES_E;t+=gridDim.x){
        size_t r0=(size_t)t*32;
        __syncthreads();
        for(int i=tid;i<1024;i+=256)sX4[i]=((const float4*)tin)[r0*32+i];
        __syncthreads();
        unsigned long long acc[4][4]={};
        #pragma unroll 2
        for(int k=0;k<DD;k++){
            ulonglong2 b0=sWu[k*64+lane],b1=sWu[k*64+32+lane];
            #pragma unroll
            for(int r=0;r<4;r++){
                unsigned long long a=pk2(sX[(rg*4+r)*DD+k]);
                fma2(acc[r][0],a,b0.x);fma2(acc[r][1],a,b0.y);
                fma2(acc[r][2],a,b1.x);fma2(acc[r][3],a,b1.y);
            }
        }
        #pragma unroll
        for(int r=0;r<4;r++){
            size_t row=r0+rg*4+r;
            float2 a0=up2(acc[r][0]),a1=up2(acc[r][1]),a2=up2(acc[r][2]),a3=up2(acc[r][3]);
            ((float4*)g_h)[row*64+lane]=make_float4(geluf(a0.x),geluf(a0.y),geluf(a1.x),geluf(a1.y));
            ((float4*)g_h)[row*64+32+lane]=make_float4(geluf(a2.x),geluf(a2.y),geluf(a3.x),geluf(a3.y));
        }
    }
}

// ---- K10: edge2 = LN(t + g_h@e1w2 + b2) -> d_out edge region (in place over t) ----
__global__ __launch_bounds__(256,1) void k_e4(const float* __restrict__ W2,const float* __restrict__ b2,
    const float* __restrict__ g,const float* __restrict__ bb,float* __restrict__ out){
    extern __shared__ float sm[];
    float* sW=sm;float* sX=sm+256*DD;
    __shared__ float sb[DD],sg[DD],sbb[DD];
    int tid=threadIdx.x,rg=tid>>5,lane=tid&31;
    float4* sW4=(float4*)sW;const float4* W4=(const float4*)W2;
    for(int i=tid;i<256*32;i+=256)sW4[i]=W4[i];
    if(tid<DD){sb[tid]=b2[tid];sg[tid]=g[tid];sbb[tid]=bb[tid];}
    const ulonglong2* sWu=(const ulonglong2*)sW;
    float4* sX4=(float4*)sX;
    for(int t=blockIdx.x;t<TILES_E;t+=gridDim.x){
        size_t r0=(size_t)t*32;
        __syncthreads();
        for(int i=tid;i<2048;i+=256)sX4[i]=((const float4*)g_h)[r0*64+i];
        __syncthreads();
        unsigned long long acc[4][2]={};
        #pragma unroll 2
        for(int k=0;k<256;k++){
            ulonglong2 bv=sWu[k*32+lane];
            #pragma unroll
            for(int r=0;r<4;r++){
                unsigned long long a=pk2(sX[(rg*4+r)*256+k]);
                fma2(acc[r][0],a,bv.x);fma2(acc[r][1],a,bv.y);
            }
        }
        #pragma unroll
        for(int r=0;r<4;r++){
            size_t row=r0+rg*4+r;
            float4 t4=((const float4*)out)[row*32+lane];
            float2 a0=up2(acc[r][0]),a1=up2(acc[r][1]);
            float v0=a0.x+sb[4*lane]+t4.x,v1=a0.y+sb[4*lane+1]+t4.y;
            float v2=a1.x+sb[4*lane+2]+t4.z,v3=a1.y+sb[4*lane+3]+t4.w;
            float mean=wsum(v0+v1+v2+v3)*(1.f/DD);
            v0-=mean;v1-=mean;v2-=mean;v3-=mean;
            float var=wsum(v0*v0+v1*v1+v2*v2+v3*v3)*(1.f/DD);
            float rs=rsqrtf(var+1e-5f);
            float4 o;
            o.x=v0*rs*sg[4*lane]+sbb[4*lane];
            o.y=v1*rs*sg[4*lane+1]+sbb[4*lane+1];
            o.z=v2*rs*sg[4*lane+2]+sbb[4*lane+2];
            o.w=v3*rs*sg[4*lane+3]+sbb[4*lane+3];
            ((float4*)out)[row*32+lane]=o;
        }
    }
}

extern "C" void kernel_launch(void* const* d_in,const int* in_sizes,int n_in,void* d_out,int out_size){
    const float* node=(const float*)d_in[0];
    const float* edge=(const float*)d_in[1];
    const float* wqkvn=(const float*)d_in[3];
    const float* wqkve=(const float*)d_in[4];
    const float* lin0w=(const float*)d_in[5];
    const float* lin0b=(const float*)d_in[6];
    const float* ln0g=(const float*)d_in[7];
    const float* ln0b=(const float*)d_in[8];
    const float* ln1g=(const float*)d_in[9];
    const float* ln1b=(const float*)d_in[10];
    const float* w1=(const float*)d_in[11];
    const float* w2=(const float*)d_in[12];
    const float* b2=(const float*)d_in[13];
    const float* e0we=(const float*)d_in[14];
    const float* e0be=(const float*)d_in[15];
    const float* e0ws=(const float*)d_in[16];
    const float* e0bs=(const float*)d_in[17];
    const float* e0wt=(const float*)d_in[18];
    const float* e0bt=(const float*)d_in[19];
    const float* e0wer=(const float*)d_in[20];
    const float* e0wec=(const float*)d_in[21];
    const float* e0w1=(const float*)d_in[22];
    const float* e0b1=(const float*)d_in[23];
    const float* e1w1=(const float*)d_in[24];
    const float* e1w2=(const float*)d_in[25];
    const float* e1b2=(const float*)d_in[26];
    const float* eln0g=(const float*)d_in[27];
    const float* eln0b=(const float*)d_in[28];
    const float* eln1g=(const float*)d_in[29];
    const float* eln1b=(const float*)d_in[30];
    float* xout=(float*)d_out;
    float* eout=(float*)d_out+(size_t)ROWS_N*DD;

    const int SM_QKVE=(DD*256+32*DD)*4;   // 147456
    const int SM_E1=(256*DD+32*256)*4;    // 163840
    const int SM_E2=(DD*DD+32*DD)*4;      // 81920
    const int SM_E3=(DD*256+32*DD)*4;     // 147456
    const int SM_E4=(256*DD+32*256)*4;    // 163840
    cudaFuncSetAttribute(k_qkve,cudaFuncAttributeMaxDynamicSharedMemorySize,SM_QKVE);
    cudaFuncSetAttribute(k_e1,cudaFuncAttributeMaxDynamicSharedMemorySize,SM_E1);
    cudaFuncSetAttribute(k_e2,cudaFuncAttributeMaxDynamicSharedMemorySize,SM_E2);
    cudaFuncSetAttribute(k_e3,cudaFuncAttributeMaxDynamicSharedMemorySize,SM_E3);
    cudaFuncSetAttribute(k_e4,cudaFuncAttributeMaxDynamicSharedMemorySize,SM_E4);

    k_qkvn<<<ROWS_N,384>>>(node,wqkvn);
    k_qkve<<<dim3(148,2),256,SM_QKVE>>>(edge,wqkve);
    k_means<<<dim3(ROWS_N,2),128>>>(edge);
    k_attn<<<ROWS_N*8/4,128>>>();
    k_node<<<ROWS_N,128>>>(node,lin0w,lin0b,ln0g,ln0b,ln1g,ln1b,w1,w2,b2,xout);
    k_PQ<<<ROWS_N,128>>>(xout,e0ws,e0bs,e0wt,e0bt,e0wer,e0wec);
    k_e1<<<148,256,SM_E1>>>(edge,e0we,e0be);
    k_e2<<<296,256,SM_E2>>>(edge,e0w1,e0b1,eln0g,eln0b,eout);
    k_e3<<<148,256,SM_E3>>>(eout,e1w1);
    k_e4<<<148,256,SM_E4>>>(e1w2,e1b2,eln1g,eln1b,eout);
}

// round 5
// speedup vs baseline: 1.3616x; 1.3616x over previous
#include <cuda_runtime.h>
#include <math.h>

#define NB 2
#define NN 384
#define DD 128
#define NSQ (NN*NN)
#define ROWS_E (NB*NSQ)      // 294912
#define ROWS_N (NB*NN)       // 768
#define T64 (ROWS_E/64)      // 4608
#define SCALE 0.08838834764831845f

__device__ __align__(256) float g_qkvn[ROWS_N*384];
__device__ __align__(256) float g_qkve[(size_t)ROWS_E*512];
__device__ __align__(256) float g_attn[ROWS_N*DD];
__device__ __align__(256) float g_mJ[ROWS_N*DD];
__device__ __align__(256) float g_mI[ROWS_N*DD];
__device__ __align__(256) float g_P[ROWS_N*DD];
__device__ __align__(256) float g_Q[ROWS_N*DD];
__device__ __align__(256) float g_buf[(size_t)ROWS_E*DD];
__device__ __align__(256) float g_h[(size_t)ROWS_E*256];

__device__ __forceinline__ unsigned long long pk2(float a){unsigned long long r;asm("mov.b64 %0,{%1,%1};":"=l"(r):"f"(a));return r;}
__device__ __forceinline__ void fma2(unsigned long long&d,unsigned long long a,unsigned long long b){asm("fma.rn.f32x2 %0,%1,%2,%0;":"+l"(d):"l"(a),"l"(b));}
__device__ __forceinline__ float2 up2(unsigned long long v){float2 f;asm("mov.b64 {%0,%1},%2;":"=f"(f.x),"=f"(f.y):"l"(v));return f;}
__device__ __forceinline__ float geluf(float x){return 0.5f*x*(1.f+erff(x*0.70710678118654752f));}
__device__ __forceinline__ float wsum(float v){
    #pragma unroll
    for(int o=16;o;o>>=1)v+=__shfl_xor_sync(0xffffffffu,v,o);return v;}
__device__ __forceinline__ float wmax(float v){
    #pragma unroll
    for(int o=16;o;o>>=1)v=fmaxf(v,__shfl_xor_sync(0xffffffffu,v,o));return v;}

// 64-row tile, 8 rows/warp/thread, NV*4 cols/lane, A vectorized (float4 broadcast)
template<int K,int NV>
__device__ __forceinline__ void mtile(const float* sX,const ulonglong2* sW,int wp,int lane,
                                      unsigned long long (&acc)[8][2*NV]){
    #pragma unroll
    for(int r=0;r<8;r++)
        #pragma unroll
        for(int v=0;v<2*NV;v++)acc[r][v]=0ull;
    #pragma unroll 2
    for(int k4=0;k4<K/4;k4++){
        float4 a4[8];
        #pragma unroll
        for(int r=0;r<8;r++)a4[r]=((const float4*)(sX+(wp*8+r)*K))[k4];
        #pragma unroll
        for(int kk=0;kk<4;kk++){
            ulonglong2 b[NV];
            #pragma unroll
            for(int v=0;v<NV;v++)b[v]=sW[(k4*4+kk)*(32*NV)+v*32+lane];
            #pragma unroll
            for(int r=0;r<8;r++){
                unsigned long long a=pk2(((const float*)&a4[r])[kk]);
                #pragma unroll
                for(int v=0;v<NV;v++){fma2(acc[r][2*v],a,b[v].x);fma2(acc[r][2*v+1],a,b[v].y);}
            }
        }
    }
}

// ---- K1: node qkv ----
__global__ __launch_bounds__(384) void k_qkvn(const float* __restrict__ node,const float* __restrict__ W){
    int row=blockIdx.x,c=threadIdx.x;
    __shared__ float s[DD];
    if(c<DD)s[c]=node[row*DD+c];
    __syncthreads();
    float a=0.f;
    #pragma unroll 8
    for(int k=0;k<DD;k++)a+=s[k]*W[k*384+c];
    g_qkvn[row*384+c]=a;
}

// ---- K2: edge qkv GEMM (N=512 via 2 halves), K=128, NV=2 ----
__global__ __launch_bounds__(256,1) void k_qkve(const float* __restrict__ edge,const float* __restrict__ W){
    extern __shared__ float sm[];
    float* sW=sm;float* sX=sm+DD*256;
    int tid=threadIdx.x,h=blockIdx.y,wp=tid>>5,lane=tid&31;
    for(int i=tid;i<DD*64;i+=256){int k=i>>6,c=i&63;((float4*)sW)[i]=((const float4*)W)[k*128+h*64+c];}
    for(int t=blockIdx.x;t<T64;t+=gridDim.x){
        size_t r0=(size_t)t*64;
        __syncthreads();
        for(int i=tid;i<2048;i+=256)((float4*)sX)[i]=((const float4*)edge)[r0*32+i];
        __syncthreads();
        unsigned long long acc[8][4];
        mtile<128,2>(sX,(const ulonglong2*)sW,wp,lane,acc);
        #pragma unroll
        for(int r=0;r<8;r++){
            size_t row=r0+wp*8+r;
            float2 a0=up2(acc[r][0]),a1=up2(acc[r][1]),a2=up2(acc[r][2]),a3=up2(acc[r][3]);
            ((float4*)g_qkve)[row*128+h*64+lane]=make_float4(a0.x,a0.y,a1.x,a1.y);
            ((float4*)g_qkve)[row*128+h*64+32+lane]=make_float4(a2.x,a2.y,a3.x,a3.y);
        }
    }
}

// ---- K3: attention, one warp per (b,h,i) ----
__global__ __launch_bounds__(128) void k_attn(){
    int w=threadIdx.x>>5,lane=threadIdx.x&31;
    int gw=blockIdx.x*4+w;
    int b=gw/(8*NN),rr=gw%(8*NN),h=rr/NN,i=rr%NN;
    const float* qb=g_qkvn+(b*NN+i)*384+h*48;
    float qv[16];
    #pragma unroll
    for(int c=0;c<16;c++)qv[c]=qb[c];
    const float* eb=g_qkve+((size_t)(b*NN+i)*NN)*512+h*64;
    float dl[12];
    #pragma unroll
    for(int t=0;t<12;t++){
        int j=lane+32*t;
        const float4* e4=(const float4*)(eb+(size_t)j*512);
        const float4* k4=(const float4*)(g_qkvn+(b*NN+j)*384+h*48+16);
        float d=0.f;
        #pragma unroll
        for(int q=0;q<4;q++){
            float4 eq=e4[q],ek=e4[4+q],kk=k4[q];
            d+=(qv[4*q]+eq.x)*(kk.x+ek.x)+(qv[4*q+1]+eq.y)*(kk.y+ek.y)
              +(qv[4*q+2]+eq.z)*(kk.z+ek.z)+(qv[4*q+3]+eq.w)*(kk.w+ek.w);
        }
        dl[t]=d*SCALE;
    }
    float m=dl[0];
    #pragma unroll
    for(int t=1;t<12;t++)m=fmaxf(m,dl[t]);
    m=wmax(m);
    float s=0.f,out[16];
    #pragma unroll
    for(int c=0;c<16;c++)out[c]=0.f;
    #pragma unroll
    for(int t=0;t<12;t++){
        int j=lane+32*t;
        float p=expf(dl[t]-m);s+=p;
        const float4* e4=(const float4*)(eb+(size_t)j*512);
        const float4* v4=(const float4*)(g_qkvn+(b*NN+j)*384+h*48+32);
        #pragma unroll
        for(int q=0;q<4;q++){
            float4 ev=e4[8+q],em=e4[12+q],vn=v4[q];
            out[4*q]+=p*(vn.x*em.x+ev.x);out[4*q+1]+=p*(vn.y*em.y+ev.y);
            out[4*q+2]+=p*(vn.z*em.z+ev.z);out[4*q+3]+=p*(vn.w*em.w+ev.w);
        }
    }
    s=wsum(s);
    float inv=1.f/s;
    #pragma unroll
    for(int c=0;c<16;c++){
        float v=wsum(out[c]);
        if(lane==0)g_attn[(b*NN+i)*DD+h*16+c]=v*inv;
    }
}

// ---- K4: node updates ----
__global__ __launch_bounds__(128) void k_node(const float* __restrict__ node,const float* __restrict__ w0,const float* __restrict__ b0,
    const float* __restrict__ g0,const float* __restrict__ be0,const float* __restrict__ g1,const float* __restrict__ be1,
    const float* __restrict__ w1,const float* __restrict__ w2,const float* __restrict__ b2,float* __restrict__ x){
    int row=blockIdx.x,c=threadIdx.x;
    __shared__ float sa[DD],sx[DD],sh[256],sr[8];
    sa[c]=g_attn[row*DD+c];
    __syncthreads();
    float y=b0[c];
    #pragma unroll 4
    for(int k=0;k<DD;k++)y+=sa[k]*w0[k*DD+c];
    float r=node[row*DD+c]+y;
    float t=wsum(r);if((c&31)==0)sr[c>>5]=t;__syncthreads();
    float mean=(sr[0]+sr[1]+sr[2]+sr[3])*(1.f/DD);
    float d=r-mean;
    t=wsum(d*d);if((c&31)==0)sr[4+(c>>5)]=t;__syncthreads();
    float x0=d*rsqrtf((sr[4]+sr[5]+sr[6]+sr[7])*(1.f/DD)+1e-5f)*g0[c]+be0[c];
    sx[c]=x0;__syncthreads();
    float h0=0.f,h1=0.f;
    #pragma unroll 4
    for(int k=0;k<DD;k++){float v=sx[k];h0+=v*w1[k*256+c];h1+=v*w1[k*256+c+128];}
    sh[c]=geluf(h0);sh[c+128]=geluf(h1);
    __syncthreads();
    float z=b2[c];
    #pragma unroll 4
    for(int k=0;k<256;k++)z+=sh[k]*w2[k*DD+c];
    float r2=x0+z;
    __syncthreads();
    t=wsum(r2);if((c&31)==0)sr[c>>5]=t;__syncthreads();
    float m2=(sr[0]+sr[1]+sr[2]+sr[3])*(1.f/DD);
    float d2=r2-m2;
    t=wsum(d2*d2);if((c&31)==0)sr[4+(c>>5)]=t;__syncthreads();
    x[row*DD+c]=d2*rsqrtf((sr[4]+sr[5]+sr[6]+sr[7])*(1.f/DD)+1e-5f)*g1[c]+be1[c];
}

// ---- K5: edge means ----
__global__ __launch_bounds__(128) void k_means(const float* __restrict__ edge){
    int bi=blockIdx.x,c=threadIdx.x,b=bi/NN,r=bi%NN;
    float s=0.f;
    if(blockIdx.y==0){
        const float* p=edge+((size_t)(b*NN+r)*NN)*DD+c;
        for(int j=0;j<NN;j++)s+=p[(size_t)j*DD];
        g_mJ[bi*DD+c]=s*(1.f/NN);
    }else{
        const float* p=edge+((size_t)b*NSQ+r)*DD+c;
        for(int i=0;i<NN;i++)s+=p[(size_t)i*NN*DD];
        g_mI[bi*DD+c]=s*(1.f/NN);
    }
}

// ---- K6: P(i), Q(j) ----
__global__ __launch_bounds__(128) void k_PQ(const float* __restrict__ x,const float* __restrict__ ws,const float* __restrict__ bs,
    const float* __restrict__ wt,const float* __restrict__ bt,const float* __restrict__ wer,const float* __restrict__ wec){
    int bi=blockIdx.x,c=threadIdx.x;
    __shared__ float sx[DD],sj[DD],si[DD];
    sx[c]=x[bi*DD+c];sj[c]=g_mJ[bi*DD+c];si[c]=g_mI[bi*DD+c];
    __syncthreads();
    float P=bs[c],Q=bt[c];
    #pragma unroll 4
    for(int k=0;k<DD;k++){
        P+=sx[k]*ws[k*DD+c]+sj[k]*wer[k*DD+c];
        Q+=sx[k]*wt[k*DD+c]+si[k]*wec[k*DD+c];
    }
    g_P[bi*DD+c]=P;g_Q[bi*DD+c]=Q;
}

// ---- K7: e1 = gelu(concat@We + be + P + Q), K=256, NV=1 ----
__global__ __launch_bounds__(256,1) void k_e1(const float* __restrict__ edge,const float* __restrict__ We,const float* __restrict__ be){
    extern __shared__ float sm[];
    float* sW=sm;float* sX=sm+256*DD;
    __shared__ float sbe[DD];
    int tid=threadIdx.x,wp=tid>>5,lane=tid&31;
    for(int i=tid;i<256*32;i+=256)((float4*)sW)[i]=((const float4*)We)[i];
    if(tid<DD)sbe[tid]=be[tid];
    for(int t=blockIdx.x;t<T64;t+=gridDim.x){
        int r0=t*64,b=r0/NSQ,rem=r0%NSQ,i=rem/NN,j0=rem%NN;
        __syncthreads();
        for(int lr=wp;lr<64;lr+=8){
            int j=j0+lr;
            ((float4*)sX)[lr*64+lane]=((const float4*)edge)[((size_t)(b*NN+i)*NN+j)*32+lane];
            ((float4*)sX)[lr*64+32+lane]=((const float4*)edge)[((size_t)(b*NN+j)*NN+i)*32+lane];
        }
        __syncthreads();
        unsigned long long acc[8][2];
        mtile<256,1>(sX,(const ulonglong2*)sW,wp,lane,acc);
        float4 p4=((const float4*)g_P)[(b*NN+i)*32+lane];
        #pragma unroll
        for(int r=0;r<8;r++){
            int lr=wp*8+r,j=j0+lr;
            float4 q4=((const float4*)g_Q)[(b*NN+j)*32+lane];
            float2 a0=up2(acc[r][0]),a1=up2(acc[r][1]);
            float4 o;
            o.x=geluf(a0.x+sbe[4*lane]+p4.x+q4.x);
            o.y=geluf(a0.y+sbe[4*lane+1]+p4.y+q4.y);
            o.z=geluf(a1.x+sbe[4*lane+2]+p4.z+q4.z);
            o.w=geluf(a1.y+sbe[4*lane+3]+p4.w+q4.w);
            ((float4*)g_buf)[((size_t)r0+lr)*32+lane]=o;
        }
    }
}

// ---- K8: t = LN(edge + g_buf@W1 + b1), K=128, NV=1 ----
__global__ __launch_bounds__(256,2) void k_e2(const float* __restrict__ edge,const float* __restrict__ W1,const float* __restrict__ b1,
    const float* __restrict__ g,const float* __restrict__ bb,float* __restrict__ tout){
    extern __shared__ float sm[];
    float* sW=sm;float* sX=sm+DD*DD;
    __shared__ float sb[DD],sg[DD],sbb[DD];
    int tid=threadIdx.x,wp=tid>>5,lane=tid&31;
    for(int i=tid;i<DD*32;i+=256)((float4*)sW)[i]=((const float4*)W1)[i];
    if(tid<DD){sb[tid]=b1[tid];sg[tid]=g[tid];sbb[tid]=bb[tid];}
    for(int t=blockIdx.x;t<T64;t+=gridDim.x){
        size_t r0=(size_t)t*64;
        __syncthreads();
        for(int i=tid;i<2048;i+=256)((float4*)sX)[i]=((const float4*)g_buf)[r0*32+i];
        __syncthreads();
        unsigned long long acc[8][2];
        mtile<128,1>(sX,(const ulonglong2*)sW,wp,lane,acc);
        #pragma unroll
        for(int r=0;r<8;r++){
            size_t row=r0+wp*8+r;
            float4 e4=((const float4*)edge)[row*32+lane];
            float2 a0=up2(acc[r][0]),a1=up2(acc[r][1]);
            float v0=a0.x+sb[4*lane]+e4.x,v1=a0.y+sb[4*lane+1]+e4.y;
            float v2=a1.x+sb[4*lane+2]+e4.z,v3=a1.y+sb[4*lane+3]+e4.w;
            float mean=wsum(v0+v1+v2+v3)*(1.f/DD);
            v0-=mean;v1-=mean;v2-=mean;v3-=mean;
            float var=wsum(v0*v0+v1*v1+v2*v2+v3*v3)*(1.f/DD);
            float rs=rsqrtf(var+1e-5f);
            float4 o;
            o.x=v0*rs*sg[4*lane]+sbb[4*lane];
            o.y=v1*rs*sg[4*lane+1]+sbb[4*lane+1];
            o.z=v2*rs*sg[4*lane+2]+sbb[4*lane+2];
            o.w=v3*rs*sg[4*lane+3]+sbb[4*lane+3];
            ((float4*)tout)[row*32+lane]=o;
        }
    }
}

// ---- K9: h = gelu(t @ e1w1), K=128, NV=2 ----
__global__ __launch_bounds__(256,1) void k_e3(const float* __restrict__ tin,const float* __restrict__ W){
    extern __shared__ float sm[];
    float* sW=sm;float* sX=sm+DD*256;
    int tid=threadIdx.x,wp=tid>>5,lane=tid&31;
    for(int i=tid;i<DD*64;i+=256)((float4*)sW)[i]=((const float4*)W)[i];
    for(int t=blockIdx.x;t<T64;t+=gridDim.x){
        size_t r0=(size_t)t*64;
        __syncthreads();
        for(int i=tid;i<2048;i+=256)((float4*)sX)[i]=((const float4*)tin)[r0*32+i];
        __syncthreads();
        unsigned long long acc[8][4];
        mtile<128,2>(sX,(const ulonglong2*)sW,wp,lane,acc);
        #pragma unroll
        for(int r=0;r<8;r++){
            size_t row=r0+wp*8+r;
            float2 a0=up2(acc[r][0]),a1=up2(acc[r][1]),a2=up2(acc[r][2]),a3=up2(acc[r][3]);
            ((float4*)g_h)[row*64+lane]=make_float4(geluf(a0.x),geluf(a0.y),geluf(a1.x),geluf(a1.y));
            ((float4*)g_h)[row*64+32+lane]=make_float4(geluf(a2.x),geluf(a2.y),geluf(a3.x),geluf(a3.y));
        }
    }
}

// ---- K10: edge2 = LN(t + g_h@e1w2 + b2), K=256, NV=1, in-place over tout ----
__global__ __launch_bounds__(256,1) void k_e4(const float* __restrict__ W2,const float* __restrict__ b2,
    const float* __restrict__ g,const float* __restrict__ bb,float* __restrict__ out){
    extern __shared__ float sm[];
    float* sW=sm;float* sX=sm+256*DD;
    __shared__ float sb[DD],sg[DD],sbb[DD];
    int tid=threadIdx.x,wp=tid>>5,lane=tid&31;
    for(int i=tid;i<256*32;i+=256)((float4*)sW)[i]=((const float4*)W2)[i];
    if(tid<DD){sb[tid]=b2[tid];sg[tid]=g[tid];sbb[tid]=bb[tid];}
    for(int t=blockIdx.x;t<T64;t+=gridDim.x){
        size_t r0=(size_t)t*64;
        __syncthreads();
        for(int i=tid;i<4096;i+=256)((float4*)sX)[i]=((const float4*)g_h)[r0*64+i];
        __syncthreads();
        unsigned long long acc[8][2];
        mtile<256,1>(sX,(const ulonglong2*)sW,wp,lane,acc);
        #pragma unroll
        for(int r=0;r<8;r++){
            size_t row=r0+wp*8+r;
            float4 t4=((const float4*)out)[row*32+lane];
            float2 a0=up2(acc[r][0]),a1=up2(acc[r][1]);
            float v0=a0.x+sb[4*lane]+t4.x,v1=a0.y+sb[4*lane+1]+t4.y;
            float v2=a1.x+sb[4*lane+2]+t4.z,v3=a1.y+sb[4*lane+3]+t4.w;
            float mean=wsum(v0+v1+v2+v3)*(1.f/DD);
            v0-=mean;v1-=mean;v2-=mean;v3-=mean;
            float var=wsum(v0*v0+v1*v1+v2*v2+v3*v3)*(1.f/DD);
            float rs=rsqrtf(var+1e-5f);
            float4 o;
            o.x=v0*rs*sg[4*lane]+sbb[4*lane];
            o.y=v1*rs*sg[4*lane+1]+sbb[4*lane+1];
            o.z=v2*rs*sg[4*lane+2]+sbb[4*lane+2];
            o.w=v3*rs*sg[4*lane+3]+sbb[4*lane+3];
            ((float4*)out)[row*32+lane]=o;
        }
    }
}

extern "C" void kernel_launch(void* const* d_in,const int* in_sizes,int n_in,void* d_out,int out_size){
    const float* node=(const float*)d_in[0];
    const float* edge=(const float*)d_in[1];
    const float* wqkvn=(const float*)d_in[3];
    const float* wqkve=(const float*)d_in[4];
    const float* lin0w=(const float*)d_in[5];
    const float* lin0b=(const float*)d_in[6];
    const float* ln0g=(const float*)d_in[7];
    const float* ln0b=(const float*)d_in[8];
    const float* ln1g=(const float*)d_in[9];
    const float* ln1b=(const float*)d_in[10];
    const float* w1=(const float*)d_in[11];
    const float* w2=(const float*)d_in[12];
    const float* b2=(const float*)d_in[13];
    const float* e0we=(const float*)d_in[14];
    const float* e0be=(const float*)d_in[15];
    const float* e0ws=(const float*)d_in[16];
    const float* e0bs=(const float*)d_in[17];
    const float* e0wt=(const float*)d_in[18];
    const float* e0bt=(const float*)d_in[19];
    const float* e0wer=(const float*)d_in[20];
    const float* e0wec=(const float*)d_in[21];
    const float* e0w1=(const float*)d_in[22];
    const float* e0b1=(const float*)d_in[23];
    const float* e1w1=(const float*)d_in[24];
    const float* e1w2=(const float*)d_in[25];
    const float* e1b2=(const float*)d_in[26];
    const float* eln0g=(const float*)d_in[27];
    const float* eln0b=(const float*)d_in[28];
    const float* eln1g=(const float*)d_in[29];
    const float* eln1b=(const float*)d_in[30];
    float* xout=(float*)d_out;
    float* eout=(float*)d_out+(size_t)ROWS_N*DD;

    const int SM_QKVE=(DD*256+64*DD)*4;   // 163840
    const int SM_E1=(256*DD+64*256)*4;    // 196608
    const int SM_E2=(DD*DD+64*DD)*4;      // 98304
    const int SM_E3=(DD*256+64*DD)*4;     // 163840
    const int SM_E4=(256*DD+64*256)*4;    // 196608
    cudaFuncSetAttribute(k_qkve,cudaFuncAttributeMaxDynamicSharedMemorySize,SM_QKVE);
    cudaFuncSetAttribute(k_e1,cudaFuncAttributeMaxDynamicSharedMemorySize,SM_E1);
    cudaFuncSetAttribute(k_e2,cudaFuncAttributeMaxDynamicSharedMemorySize,SM_E2);
    cudaFuncSetAttribute(k_e3,cudaFuncAttributeMaxDynamicSharedMemorySize,SM_E3);
    cudaFuncSetAttribute(k_e4,cudaFuncAttributeMaxDynamicSharedMemorySize,SM_E4);

    k_qkvn<<<ROWS_N,384>>>(node,wqkvn);
    k_qkve<<<dim3(148,2),256,SM_QKVE>>>(edge,wqkve);
    k_means<<<dim3(ROWS_N,2),128>>>(edge);
    k_attn<<<ROWS_N*8/4,128>>>();
    k_node<<<ROWS_N,128>>>(node,lin0w,lin0b,ln0g,ln0b,ln1g,ln1b,w1,w2,b2,xout);
    k_PQ<<<ROWS_N,128>>>(xout,e0ws,e0bs,e0wt,e0bt,e0wer,e0wec);
    k_e1<<<148,256,SM_E1>>>(edge,e0we,e0be);
    k_e2<<<296,256,SM_E2>>>(edge,e0w1,e0b1,eln0g,eln0b,eout);
    k_e3<<<148,256,SM_E3>>>(eout,e1w1);
    k_e4<<<148,256,SM_E4>>>(e1w2,e1b2,eln1g,eln1b,eout);
}